// round 13
// baseline (speedup 1.0000x reference)
#include <cuda_runtime.h>

// EPG / RF-spoiled SPGR, round 13.
// vs R12 (1614us, fma-pipe-bound at 75.7%): three fma-pipe diet cuts:
//  (1) nsA = sA ^ signmask on ALU pipe (coefficient path, off the state
//      chain — unlike R8's regression) instead of a 3rd f2mul;
//  (2) spec complex-multiply packed: table stores {c,c,s,-s} so
//      spec = f2fma(swap(Qhi), {s,-s}, f2mul(Qhi, {c,c})) — 2 packed ops
//      replacing 4 scalar fma-pipe ops;
//  (3) dead nE2P constant dropped.
// State (P,Q,Z)=(F̂p,F̂m,Z), rotating frame; G = c2*(P-Q) - i*sa*Z,
// Fp'' = Q+G, Fm'' = P-G. Lazy truncation: only Fp[49] killed pre-shift.
// One warp/voxel; lane l holds packed pair {k=2l,k=2l+1} (f32x2).

#define FULLMASK 0xffffffffu
typedef unsigned long long u64;
#define NP 200
#define SGN2 0x8000000080000000ULL

// Staging (written by init kernel), then copied D2D into __constant__.
__device__    float4 g_tab4[NP];   // {cos d, cos d, sin d, sin d}
__device__    float4 g_spec4[NP];  // {cos 2phi', cos 2phi', sin 2phi', -sin 2phi'}
__constant__  float4 c_tab4[NP];
__constant__  float4 c_spec4[NP];

__global__ void trig_init_kernel() {
    int p = threadIdx.x + blockIdx.x * blockDim.x;
    if (p >= NP) return;
    const float SPOIL = 2.0420352248333655f;  // float32(deg2rad(117))
    float phi = 0.f, inc = 0.f;
    for (int j = 0; j < p; ++j) { inc += SPOIL; phi += inc; }   // phi_p, exact ref order
    float phin = phi + (inc + SPOIL);                            // phi_{p+1}
    float d = phin - phi;                                        // exact subtraction
    float sd, cd;  sincosf(d, &sd, &cd);
    float s2p, c2p; sincosf(2.0f * phin, &s2p, &c2p);
    g_tab4[p]  = make_float4(cd, cd, sd, sd);
    g_spec4[p] = make_float4(c2p, c2p, s2p, -s2p);
}

static __device__ __forceinline__ u64 pk2(float lo, float hi) {
    u64 r; asm("mov.b64 %0, {%1, %2};" : "=l"(r) : "f"(lo), "f"(hi)); return r;
}
static __device__ __forceinline__ void upk2(u64 v, float& lo, float& hi) {
    asm("mov.b64 {%0, %1}, %2;" : "=f"(lo), "=f"(hi) : "l"(v));
}
static __device__ __forceinline__ u64 f2fma(u64 a, u64 b, u64 c) {
    u64 d; asm("fma.rn.f32x2 %0, %1, %2, %3;" : "=l"(d) : "l"(a), "l"(b), "l"(c)); return d;
}
static __device__ __forceinline__ u64 f2mul(u64 a, u64 b) {
    u64 d; asm("mul.rn.f32x2 %0, %1, %2;" : "=l"(d) : "l"(a), "l"(b)); return d;
}
static __device__ __forceinline__ u64 f2add(u64 a, u64 b) {
    u64 d; asm("add.rn.f32x2 %0, %1, %2;" : "=l"(d) : "l"(a), "l"(b)); return d;
}

__global__ void __launch_bounds__(256)
epg_kernel(const float* __restrict__ T1, const float* __restrict__ T2,
           const float* __restrict__ alpha, const float* __restrict__ TR,
           float* __restrict__ out, int n)
{
    const int v    = (blockIdx.x * blockDim.x + threadIdx.x) >> 5;
    const int lane = threadIdx.x & 31;
    if (v >= n) return;

    const float TRv = TR[0];
    const float E1  = expf(-TRv / T1[v]);
    const float E2  = expf(-TRv / T2[v]);
    const float a   = alpha[v];
    float sa, ca; sincosf(a, &sa, &ca);
    const float c2    = 0.5f * (1.0f + ca);   // cos^2(a/2)
    const float saE1h = 0.5f * sa * E1;
    const float caE1  = ca * E1;

    const u64 c2P     = pk2(c2, c2);
    const u64 saP     = pk2(sa, sa);
    const u64 nsaP    = pk2(-sa, -sa);
    const u64 caE1P   = pk2(caE1, caE1);
    const u64 saE1hP  = pk2(saE1h, saE1h);
    const u64 nsaE1hP = pk2(-saE1h, -saE1h);
    const u64 E2P     = pk2(E2, E2);
    const u64 nOneP   = pk2(-1.f, -1.f);
    const u64 boostP  = pk2(lane == 0 ? 1.f - E1 : 0.f, 0.f);

    // Lazy truncation: only Fp[49] (lane 24, hi word) must be killed
    // pre-shift; all k>=50 states remain identically zero by induction.
    const u64 mK = (lane == 24) ? 0x00000000ffffffffull : ~0ull;

    // State {k=2l, k=2l+1}: P = F̂p, Q = F̂m, Z (rotating frame phi_p).
    u64 Pr = 0, Pi = 0, Qr = 0, Qi = 0;
    u64 Zr = pk2(lane == 0 ? 1.f : 0.f, 0.f), Zi = 0;

    #pragma unroll 4
    for (int p = 0; p < NP - 1; ++p) {
        const float4 t = c_tab4[p];                 // {cd,cd,sd,sd} (uniform LDC)
        const u64 cdP = pk2(t.x, t.y);
        const u64 sdP = pk2(t.z, t.w);
        const float4 s4 = c_spec4[p];               // {c,c,s,-s}
        const u64 csP = pk2(s4.x, s4.y);
        const u64 ssP = pk2(s4.z, s4.w);

        // Coefficients: A = E2 * e^{-i d}  (Ar = cA, Ai = -sA)
        const u64 cA  = f2mul(E2P, cdP);
        const u64 sA  = f2mul(E2P, sdP);
        const u64 nsA = sA ^ SGN2;                  // ALU negate, off the state chain

        // D = P - Q
        const u64 Dr = f2fma(nOneP, Qr, Pr);
        const u64 Di = f2fma(nOneP, Qi, Pi);

        // G = c2*D - i*sa*Z :  Gr = c2*Dr + sa*Zi ; Gi = c2*Di - sa*Zr
        const u64 Gr = f2fma(c2P, Dr, f2mul(saP,  Zi));
        const u64 Gi = f2fma(c2P, Di, f2mul(nsaP, Zr));

        // Z_next = E1*(ca*Z - 0.5i*sa*D) + boost
        const u64 nZr = f2fma(caE1P, Zr, f2fma(saE1hP, Di, boostP));
        const u64 nZi = f2fma(caE1P, Zi, f2mul(nsaE1hP, Dr));

        // Fp'' = Q + G ;  Fm'' = P - G
        const u64 Fpr = f2add(Qr, Gr);
        const u64 Fpi = f2add(Qi, Gi);
        const u64 Fmr = f2fma(nOneP, Gr, Pr);
        const u64 Fmi = f2fma(nOneP, Gi, Pi);

        // Pre-shift: nP = A (.) Fp'' (kill Fp[49]) ;  nQ = conj(A) (.) Fm''
        const u64 nPr = f2fma(sA,  Fpi, f2mul(cA, Fpr)) & mK;
        const u64 nPi = f2fma(nsA, Fpr, f2mul(cA, Fpi)) & mK;
        const u64 nQr = f2fma(nsA, Fmi, f2mul(cA, Fmr));
        const u64 nQi = f2fma(sA,  Fmr, f2mul(cA, Fmi));

        // Shift: Fp'[2l]=nP[2l-1] (prev hi; lane0 -> spec), Fp'[2l+1]=nP[2l]
        //        Fm'[2l]=nQ[2l+1] (own hi),  Fm'[2l+1]=nQ[2l+2] (next lo)
        float Plo_r, Phi_r, Plo_i, Phi_i;
        upk2(nPr, Plo_r, Phi_r); upk2(nPi, Plo_i, Phi_i);
        float Qlo_r, Qhi_r, Qlo_i, Qhi_i;
        upk2(nQr, Qlo_r, Qhi_r); upk2(nQi, Qlo_i, Qhi_i);

        float su_r = __shfl_up_sync(FULLMASK, Phi_r, 1);
        float su_i = __shfl_up_sync(FULLMASK, Phi_i, 1);
        float sd_r = __shfl_down_sync(FULLMASK, Qlo_r, 1);
        float sd_i = __shfl_down_sync(FULLMASK, Qlo_i, 1);

        // lane0 Fp'[0] = nQ[1] * e^{-2i phi_{p+1}}, packed 2-op complex mul:
        //   lo = Qhi_r*c + Qhi_i*s ;  hi = Qhi_i*c - Qhi_r*s
        const u64 uQ = pk2(Qhi_r, Qhi_i);
        const u64 wQ = pk2(Qhi_i, Qhi_r);
        float spec_r, spec_i;
        upk2(f2fma(wQ, ssP, f2mul(uQ, csP)), spec_r, spec_i);
        if (lane == 0) { su_r = spec_r; su_i = spec_i; }

        Pr = pk2(su_r, Plo_r);
        Pi = pk2(su_i, Plo_i);
        Qr = pk2(Qhi_r, sd_r);
        Qi = pk2(Qhi_i, sd_i);
        Zr = nZr; Zi = nZi;
    }

    // Final pulse (p = NP-1): signal = |Fp''[0]| = |(Q + G)[0]| (lane 0, lo).
    {
        float P0r, P0i, Q0r, Q0i, Z0r, Z0i, dum;
        upk2(Pr, P0r, dum); upk2(Pi, P0i, dum);
        upk2(Qr, Q0r, dum); upk2(Qi, Q0i, dum);
        upk2(Zr, Z0r, dum); upk2(Zi, Z0i, dum);
        const float D0r = P0r - Q0r;
        const float D0i = P0i - Q0i;
        const float G0r = c2 * D0r + sa * Z0i;
        const float G0i = c2 * D0i - sa * Z0r;
        const float Fp0r = Q0r + G0r;
        const float Fp0i = Q0i + G0i;
        if (lane == 0) out[v] = sqrtf(Fp0r * Fp0r + Fp0i * Fp0i);
    }
}

extern "C" void kernel_launch(void* const* d_in, const int* in_sizes, int n_in,
                              void* d_out, int out_size)
{
    const float* T1    = (const float*)d_in[0];
    const float* T2    = (const float*)d_in[1];
    const float* alpha = (const float*)d_in[2];
    const float* TR    = (const float*)d_in[3];
    float* out = (float*)d_out;

    const int n = in_sizes[0];
    trig_init_kernel<<<1, 256>>>();

    // Resolve REAL device addresses of the symbols (address query only), then
    // async D2D copy staging -> constant bank (capturable memcpy nodes).
    void *p_ctab = 0, *p_gtab = 0, *p_cspec = 0, *p_gspec = 0;
    cudaGetSymbolAddress(&p_ctab,  c_tab4);
    cudaGetSymbolAddress(&p_gtab,  g_tab4);
    cudaGetSymbolAddress(&p_cspec, c_spec4);
    cudaGetSymbolAddress(&p_gspec, g_spec4);
    cudaMemcpyAsync(p_ctab,  p_gtab,  sizeof(float4) * NP, cudaMemcpyDeviceToDevice);
    cudaMemcpyAsync(p_cspec, p_gspec, sizeof(float4) * NP, cudaMemcpyDeviceToDevice);

    const int threads = 256;  // 8 warps/block
    const int wpb = threads / 32;
    const int blocks = (n + wpb - 1) / wpb;
    epg_kernel<<<blocks, threads>>>(T1, T2, alpha, TR, out, n);
}

// round 14
// speedup vs baseline: 1.1698x; 1.1698x over previous
#include <cuda_runtime.h>

// EPG / RF-spoiled SPGR, round 14. Base = R12 (1614us) math, new layout:
// TWO voxels per warp, 16-lane groups, FOUR states per lane (k=4gl..4gl+3,
// two f32x2 registers per component). Shift-by-1 is 3/4 in-lane repack and
// only ONE word crosses lanes per direction -> 4 width-16 SHFLs per
// warp-pulse = 2 per voxel-pulse (was 4). A-coefficients shared across both
// slots (fma ops/voxel 29 -> 25.5). R13's XOR + packed-spec reverted.
//
// Rotating frame: state (P,Q,Z)=(F̂p,F̂m,Z); G = c2*(P-Q) - i*sa*Z,
// Fp''=Q+G, Fm''=P-G; phase enters as A=E2*e^{-i delta_p} pre-shift and
// e^{-2i phi_{p+1}} on the Fm[1]->Fp[0] element (group-lane-0 local).
// Lazy truncation: only Fp[49] (gl=12, slot-a hi) killed pre-shift; all
// k>=50 states stay identically zero by induction (this also makes the
// width-16 shfl_down clamp at gl=15 return an exact zero).

#define FULLMASK 0xffffffffu
typedef unsigned long long u64;
#define NP 200

__device__    float4 g_tab4[NP];   // {cos d, cos d, sin d, sin d}
__device__    float2 g_spec2[NP];  // {cos 2phi', sin 2phi'}
__constant__  float4 c_tab4[NP];
__constant__  float2 c_spec2[NP];

__global__ void trig_init_kernel() {
    int p = threadIdx.x + blockIdx.x * blockDim.x;
    if (p >= NP) return;
    const float SPOIL = 2.0420352248333655f;  // float32(deg2rad(117))
    float phi = 0.f, inc = 0.f;
    for (int j = 0; j < p; ++j) { inc += SPOIL; phi += inc; }   // phi_p, exact ref order
    float phin = phi + (inc + SPOIL);                            // phi_{p+1}
    float d = phin - phi;                                        // exact subtraction
    float sd, cd;  sincosf(d, &sd, &cd);
    float s2p, c2p; sincosf(2.0f * phin, &s2p, &c2p);
    g_tab4[p]  = make_float4(cd, cd, sd, sd);
    g_spec2[p] = make_float2(c2p, s2p);
}

static __device__ __forceinline__ u64 pk2(float lo, float hi) {
    u64 r; asm("mov.b64 %0, {%1, %2};" : "=l"(r) : "f"(lo), "f"(hi)); return r;
}
static __device__ __forceinline__ void upk2(u64 v, float& lo, float& hi) {
    asm("mov.b64 {%0, %1}, %2;" : "=f"(lo), "=f"(hi) : "l"(v));
}
static __device__ __forceinline__ u64 f2fma(u64 a, u64 b, u64 c) {
    u64 d; asm("fma.rn.f32x2 %0, %1, %2, %3;" : "=l"(d) : "l"(a), "l"(b), "l"(c)); return d;
}
static __device__ __forceinline__ u64 f2mul(u64 a, u64 b) {
    u64 d; asm("mul.rn.f32x2 %0, %1, %2;" : "=l"(d) : "l"(a), "l"(b)); return d;
}
static __device__ __forceinline__ u64 f2add(u64 a, u64 b) {
    u64 d; asm("add.rn.f32x2 %0, %1, %2;" : "=l"(d) : "l"(a), "l"(b)); return d;
}

__global__ void __launch_bounds__(256)
epg_kernel(const float* __restrict__ T1, const float* __restrict__ T2,
           const float* __restrict__ alpha, const float* __restrict__ TR,
           float* __restrict__ out, int n)
{
    const int wid  = (blockIdx.x * blockDim.x + threadIdx.x) >> 5;
    const int lane = threadIdx.x & 31;
    const int gl   = lane & 15;               // lane within 16-lane group
    const int v    = wid * 2 + (lane >> 4);   // this lane's voxel
    const int vc   = v < n ? v : n - 1;       // clamped for loads

    const float TRv = TR[0];
    const float E1  = expf(-TRv / T1[vc]);
    const float E2  = expf(-TRv / T2[vc]);
    const float a   = alpha[vc];
    float sa, ca; sincosf(a, &sa, &ca);
    const float c2    = 0.5f * (1.0f + ca);   // cos^2(a/2)
    const float saE1h = 0.5f * sa * E1;
    const float caE1  = ca * E1;

    const u64 c2P     = pk2(c2, c2);
    const u64 saP     = pk2(sa, sa);
    const u64 nsaP    = pk2(-sa, -sa);
    const u64 caE1P   = pk2(caE1, caE1);
    const u64 saE1hP  = pk2(saE1h, saE1h);
    const u64 nsaE1hP = pk2(-saE1h, -saE1h);
    const u64 E2P     = pk2(E2, E2);
    const u64 nE2P    = pk2(-E2, -E2);
    const u64 nOneP   = pk2(-1.f, -1.f);
    const u64 boostP  = pk2(gl == 0 ? 1.f - E1 : 0.f, 0.f);

    // Lazy truncation: Fp[49] lives at gl==12, slot a, hi word.
    const u64 mK = (gl == 12) ? 0x00000000ffffffffull : ~0ull;

    // State: slot a = {k=4gl, 4gl+1}, slot b = {k=4gl+2, 4gl+3}.
    u64 Par = 0, Pai = 0, Pbr = 0, Pbi = 0;
    u64 Qar = 0, Qai = 0, Qbr = 0, Qbi = 0;
    u64 Zar = pk2(gl == 0 ? 1.f : 0.f, 0.f), Zai = 0;
    u64 Zbr = 0, Zbi = 0;

    #pragma unroll 2
    for (int p = 0; p < NP - 1; ++p) {
        const float4 t = c_tab4[p];                 // {cd,cd,sd,sd} (uniform LDC)
        const u64 cdP = pk2(t.x, t.y);
        const u64 sdP = pk2(t.z, t.w);
        const float2 sp = c_spec2[p];               // {cos 2phi', sin 2phi'}

        // Coefficients (shared by both slots): A = E2 * e^{-i d}
        const u64 cA  = f2mul(E2P, cdP);
        const u64 sA  = f2mul(E2P, sdP);
        const u64 nsA = f2mul(nE2P, sdP);

        // ---- slot a ----
        const u64 Dar = f2fma(nOneP, Qar, Par);
        const u64 Dai = f2fma(nOneP, Qai, Pai);
        const u64 Gar = f2fma(c2P, Dar, f2mul(saP,  Zai));
        const u64 Gai = f2fma(c2P, Dai, f2mul(nsaP, Zar));
        const u64 nZar = f2fma(caE1P, Zar, f2fma(saE1hP, Dai, boostP));
        const u64 nZai = f2fma(caE1P, Zai, f2mul(nsaE1hP, Dar));
        const u64 Fpar = f2add(Qar, Gar);
        const u64 Fpai = f2add(Qai, Gai);
        const u64 Fmar = f2fma(nOneP, Gar, Par);
        const u64 Fmai = f2fma(nOneP, Gai, Pai);
        const u64 nPar = f2fma(sA,  Fpai, f2mul(cA, Fpar)) & mK;
        const u64 nPai = f2fma(nsA, Fpar, f2mul(cA, Fpai)) & mK;
        const u64 nQar = f2fma(nsA, Fmai, f2mul(cA, Fmar));
        const u64 nQai = f2fma(sA,  Fmar, f2mul(cA, Fmai));

        // ---- slot b ----
        const u64 Dbr = f2fma(nOneP, Qbr, Pbr);
        const u64 Dbi = f2fma(nOneP, Qbi, Pbi);
        const u64 Gbr = f2fma(c2P, Dbr, f2mul(saP,  Zbi));
        const u64 Gbi = f2fma(c2P, Dbi, f2mul(nsaP, Zbr));
        const u64 nZbr = f2fma(caE1P, Zbr, f2mul(saE1hP, Dbi));
        const u64 nZbi = f2fma(caE1P, Zbi, f2mul(nsaE1hP, Dbr));
        const u64 Fpbr = f2add(Qbr, Gbr);
        const u64 Fpbi = f2add(Qbi, Gbi);
        const u64 Fmbr = f2fma(nOneP, Gbr, Pbr);
        const u64 Fmbi = f2fma(nOneP, Gbi, Pbi);
        const u64 nPbr = f2fma(sA,  Fpbi, f2mul(cA, Fpbr));
        const u64 nPbi = f2fma(nsA, Fpbr, f2mul(cA, Fpbi));
        const u64 nQbr = f2fma(nsA, Fmbi, f2mul(cA, Fmbr));
        const u64 nQbi = f2fma(sA,  Fmbr, f2mul(cA, Fmbi));

        // ---- shift ----
        // Fp'[4gl] = Fp[4gl-1] (prev lane's b-hi; gl0 -> spec)
        // Fp'[4gl+1..3] = in-lane {a-lo, a-hi, b-lo}
        // Fm'[4gl..2] = in-lane {a-hi, b-lo, b-hi}; Fm'[4gl+3] = next lane's a-lo
        float PalR, PahR, PalI, PahI, PblR, PbhR, PblI, PbhI;
        upk2(nPar, PalR, PahR); upk2(nPai, PalI, PahI);
        upk2(nPbr, PblR, PbhR); upk2(nPbi, PblI, PbhI);
        float QalR, QahR, QalI, QahI, QblR, QbhR, QblI, QbhI;
        upk2(nQar, QalR, QahR); upk2(nQai, QalI, QahI);
        upk2(nQbr, QblR, QbhR); upk2(nQbi, QblI, QbhI);

        float su_r = __shfl_up_sync(FULLMASK, PbhR, 1, 16);
        float su_i = __shfl_up_sync(FULLMASK, PbhI, 1, 16);
        float sd_r = __shfl_down_sync(FULLMASK, QalR, 1, 16);
        float sd_i = __shfl_down_sync(FULLMASK, QalI, 1, 16);
        // gl==15: width-16 clamp returns own QalR = Fm[60] == 0 (induction). OK.

        // gl==0: Fp'[0] = nQ[1] * e^{-2i phi'}  (nQ[1] = own a-hi)
        const float spec_r = QahR * sp.x + QahI * sp.y;
        const float spec_i = QahI * sp.x - QahR * sp.y;
        if (gl == 0) { su_r = spec_r; su_i = spec_i; }

        Par = pk2(su_r, PalR);  Pai = pk2(su_i, PalI);
        Pbr = pk2(PahR, PblR);  Pbi = pk2(PahI, PblI);
        Qar = pk2(QahR, QblR);  Qai = pk2(QahI, QblI);
        Qbr = pk2(QbhR, sd_r);  Qbi = pk2(QbhI, sd_i);
        Zar = nZar; Zai = nZai; Zbr = nZbr; Zbi = nZbi;
    }

    // Final pulse: signal = |Fp''[0]| = |(Q + G)[0]|  (gl==0, slot a, lo word)
    {
        float P0r, P0i, Q0r, Q0i, Z0r, Z0i, dum;
        upk2(Par, P0r, dum); upk2(Pai, P0i, dum);
        upk2(Qar, Q0r, dum); upk2(Qai, Q0i, dum);
        upk2(Zar, Z0r, dum); upk2(Zai, Z0i, dum);
        const float D0r = P0r - Q0r;
        const float D0i = P0i - Q0i;
        const float G0r = c2 * D0r + sa * Z0i;
        const float G0i = c2 * D0i - sa * Z0r;
        const float Fp0r = Q0r + G0r;
        const float Fp0i = Q0i + G0i;
        if (gl == 0 && v < n) out[v] = sqrtf(Fp0r * Fp0r + Fp0i * Fp0i);
    }
}

extern "C" void kernel_launch(void* const* d_in, const int* in_sizes, int n_in,
                              void* d_out, int out_size)
{
    const float* T1    = (const float*)d_in[0];
    const float* T2    = (const float*)d_in[1];
    const float* alpha = (const float*)d_in[2];
    const float* TR    = (const float*)d_in[3];
    float* out = (float*)d_out;

    const int n = in_sizes[0];
    trig_init_kernel<<<1, 256>>>();

    void *p_ctab = 0, *p_gtab = 0, *p_cspec = 0, *p_gspec = 0;
    cudaGetSymbolAddress(&p_ctab,  c_tab4);
    cudaGetSymbolAddress(&p_gtab,  g_tab4);
    cudaGetSymbolAddress(&p_cspec, c_spec2);
    cudaGetSymbolAddress(&p_gspec, g_spec2);
    cudaMemcpyAsync(p_ctab,  p_gtab,  sizeof(float4) * NP, cudaMemcpyDeviceToDevice);
    cudaMemcpyAsync(p_cspec, p_gspec, sizeof(float2) * NP, cudaMemcpyDeviceToDevice);

    const int threads = 256;                   // 8 warps = 16 voxels per block
    const int vpb = (threads / 32) * 2;
    const int blocks = (n + vpb - 1) / vpb;
    epg_kernel<<<blocks, threads>>>(T1, T2, alpha, TR, out, n);
}

// round 15
// speedup vs baseline: 1.2134x; 1.0373x over previous
#include <cuda_runtime.h>

// EPG / RF-spoiled SPGR, round 15.
// vs R14 (1423us): (a) FOUR voxels per warp, 8-lane groups, EIGHT states per
// lane (4 slots of f32x2) -> 4 width-8 SHFLs per warp-pulse = 1 per
// voxel-pulse; coefficients shared across 4 slots. (b) Y = -2iZ substitution:
// G = c2*D + (sa/2)*Y, Y' = caE1*Y - saE1*D (+ boost -2(1-E1) into Yi[0]) —
// componentwise-real couplings, no r/i swaps, 2 fewer packed constants.
// Rotating frame, state (P,Q,Y); Fp''=Q+G, Fm''=P-G; phase A=E2*e^{-i d}
// pre-shift; spec e^{-2i phi'} on Fm[1]->Fp[0] (group-lane-0 local).
// Lazy truncation: only Fp[49] (gl=6, slot-a hi) killed pre-shift; k>=50
// states stay zero by induction (also covers both shfl width-8 clamps).

#define FULLMASK 0xffffffffu
typedef unsigned long long u64;
#define NP 200

__device__    float4 g_tab4[NP];   // {cos d, cos d, sin d, sin d}
__device__    float2 g_spec2[NP];  // {cos 2phi', sin 2phi'}
__constant__  float4 c_tab4[NP];
__constant__  float2 c_spec2[NP];

__global__ void trig_init_kernel() {
    int p = threadIdx.x + blockIdx.x * blockDim.x;
    if (p >= NP) return;
    const float SPOIL = 2.0420352248333655f;  // float32(deg2rad(117))
    float phi = 0.f, inc = 0.f;
    for (int j = 0; j < p; ++j) { inc += SPOIL; phi += inc; }   // phi_p, exact ref order
    float phin = phi + (inc + SPOIL);                            // phi_{p+1}
    float d = phin - phi;                                        // exact subtraction
    float sd, cd;  sincosf(d, &sd, &cd);
    float s2p, c2p; sincosf(2.0f * phin, &s2p, &c2p);
    g_tab4[p]  = make_float4(cd, cd, sd, sd);
    g_spec2[p] = make_float2(c2p, s2p);
}

static __device__ __forceinline__ u64 pk2(float lo, float hi) {
    u64 r; asm("mov.b64 %0, {%1, %2};" : "=l"(r) : "f"(lo), "f"(hi)); return r;
}
static __device__ __forceinline__ void upk2(u64 v, float& lo, float& hi) {
    asm("mov.b64 {%0, %1}, %2;" : "=f"(lo), "=f"(hi) : "l"(v));
}
static __device__ __forceinline__ u64 f2fma(u64 a, u64 b, u64 c) {
    u64 d; asm("fma.rn.f32x2 %0, %1, %2, %3;" : "=l"(d) : "l"(a), "l"(b), "l"(c)); return d;
}
static __device__ __forceinline__ u64 f2mul(u64 a, u64 b) {
    u64 d; asm("mul.rn.f32x2 %0, %1, %2;" : "=l"(d) : "l"(a), "l"(b)); return d;
}
static __device__ __forceinline__ u64 f2add(u64 a, u64 b) {
    u64 d; asm("add.rn.f32x2 %0, %1, %2;" : "=l"(d) : "l"(a), "l"(b)); return d;
}

__global__ void __launch_bounds__(256)
epg_kernel(const float* __restrict__ T1, const float* __restrict__ T2,
           const float* __restrict__ alpha, const float* __restrict__ TR,
           float* __restrict__ out, int n)
{
    const int wid  = (blockIdx.x * blockDim.x + threadIdx.x) >> 5;
    const int lane = threadIdx.x & 31;
    const int gl   = lane & 7;                // lane within 8-lane group
    const int v    = wid * 4 + (lane >> 3);   // this lane's voxel
    const int vc   = v < n ? v : n - 1;       // clamped for loads

    const float TRv = TR[0];
    const float E1  = expf(-TRv / T1[vc]);
    const float E2  = expf(-TRv / T2[vc]);
    const float a   = alpha[vc];
    float sa, ca; sincosf(a, &sa, &ca);
    const float c2   = 0.5f * (1.0f + ca);    // cos^2(a/2)
    const float sah  = 0.5f * sa;
    const float caE1 = ca * E1;
    const float saE1 = sa * E1;

    const u64 c2P    = pk2(c2, c2);
    const u64 sahP   = pk2(sah, sah);
    const u64 caE1P  = pk2(caE1, caE1);
    const u64 nsaE1P = pk2(-saE1, -saE1);
    const u64 E2P    = pk2(E2, E2);
    const u64 nE2P   = pk2(-E2, -E2);
    const u64 nOneP  = pk2(-1.f, -1.f);
    const u64 boostP = pk2(gl == 0 ? -2.0f * (1.0f - E1) : 0.f, 0.f);

    // Lazy truncation: Fp[49] = gl 6, slot a, hi word.
    const u64 mK = (gl == 6) ? 0x00000000ffffffffull : ~0ull;

    // State: slots a..d = {k=8gl+0,1}, {+2,3}, {+4,5}, {+6,7}. Y = -2iZ.
    u64 Par = 0, Pai = 0, Pbr = 0, Pbi = 0, Pcr = 0, Pci = 0, Pdr = 0, Pdi = 0;
    u64 Qar = 0, Qai = 0, Qbr = 0, Qbi = 0, Qcr = 0, Qci = 0, Qdr = 0, Qdi = 0;
    u64 Yar = 0, Yai = pk2(gl == 0 ? -2.0f : 0.f, 0.f);
    u64 Ybr = 0, Ybi = 0, Ycr = 0, Yci = 0, Ydr = 0, Ydi = 0;

    #pragma unroll 2
    for (int p = 0; p < NP - 1; ++p) {
        const float4 t = c_tab4[p];                 // {cd,cd,sd,sd} (uniform LDC)
        const u64 cdP = pk2(t.x, t.y);
        const u64 sdP = pk2(t.z, t.w);
        const float2 sp = c_spec2[p];               // {cos 2phi', sin 2phi'}

        // Coefficients (shared by all 4 slots): A = E2 * e^{-i d}
        const u64 cA  = f2mul(E2P, cdP);
        const u64 sA  = f2mul(E2P, sdP);
        const u64 nsA = f2mul(nE2P, sdP);

        // ---- slot a (carries boost in Yi) ----
        const u64 Dar = f2fma(nOneP, Qar, Par);
        const u64 Dai = f2fma(nOneP, Qai, Pai);
        const u64 Gar = f2fma(c2P, Dar, f2mul(sahP, Yar));
        const u64 Gai = f2fma(c2P, Dai, f2mul(sahP, Yai));
        const u64 nYar = f2fma(caE1P, Yar, f2mul(nsaE1P, Dar));
        const u64 nYai = f2fma(caE1P, Yai, f2fma(nsaE1P, Dai, boostP));
        const u64 Fpar = f2add(Qar, Gar);
        const u64 Fpai = f2add(Qai, Gai);
        const u64 Fmar = f2fma(nOneP, Gar, Par);
        const u64 Fmai = f2fma(nOneP, Gai, Pai);
        const u64 nPar = f2fma(sA,  Fpai, f2mul(cA, Fpar)) & mK;
        const u64 nPai = f2fma(nsA, Fpar, f2mul(cA, Fpai)) & mK;
        const u64 nQar = f2fma(nsA, Fmai, f2mul(cA, Fmar));
        const u64 nQai = f2fma(sA,  Fmar, f2mul(cA, Fmai));

        // ---- slot b ----
        const u64 Dbr = f2fma(nOneP, Qbr, Pbr);
        const u64 Dbi = f2fma(nOneP, Qbi, Pbi);
        const u64 Gbr = f2fma(c2P, Dbr, f2mul(sahP, Ybr));
        const u64 Gbi = f2fma(c2P, Dbi, f2mul(sahP, Ybi));
        const u64 nYbr = f2fma(caE1P, Ybr, f2mul(nsaE1P, Dbr));
        const u64 nYbi = f2fma(caE1P, Ybi, f2mul(nsaE1P, Dbi));
        const u64 Fpbr = f2add(Qbr, Gbr);
        const u64 Fpbi = f2add(Qbi, Gbi);
        const u64 Fmbr = f2fma(nOneP, Gbr, Pbr);
        const u64 Fmbi = f2fma(nOneP, Gbi, Pbi);
        const u64 nPbr = f2fma(sA,  Fpbi, f2mul(cA, Fpbr));
        const u64 nPbi = f2fma(nsA, Fpbr, f2mul(cA, Fpbi));
        const u64 nQbr = f2fma(nsA, Fmbi, f2mul(cA, Fmbr));
        const u64 nQbi = f2fma(sA,  Fmbr, f2mul(cA, Fmbi));

        // ---- slot c ----
        const u64 Dcr = f2fma(nOneP, Qcr, Pcr);
        const u64 Dci = f2fma(nOneP, Qci, Pci);
        const u64 Gcr = f2fma(c2P, Dcr, f2mul(sahP, Ycr));
        const u64 Gci = f2fma(c2P, Dci, f2mul(sahP, Yci));
        const u64 nYcr = f2fma(caE1P, Ycr, f2mul(nsaE1P, Dcr));
        const u64 nYci = f2fma(caE1P, Yci, f2mul(nsaE1P, Dci));
        const u64 Fpcr = f2add(Qcr, Gcr);
        const u64 Fpci = f2add(Qci, Gci);
        const u64 Fmcr = f2fma(nOneP, Gcr, Pcr);
        const u64 Fmci = f2fma(nOneP, Gci, Pci);
        const u64 nPcr = f2fma(sA,  Fpci, f2mul(cA, Fpcr));
        const u64 nPci = f2fma(nsA, Fpcr, f2mul(cA, Fpci));
        const u64 nQcr = f2fma(nsA, Fmci, f2mul(cA, Fmcr));
        const u64 nQci = f2fma(sA,  Fmcr, f2mul(cA, Fmci));

        // ---- slot d ----
        const u64 Ddr = f2fma(nOneP, Qdr, Pdr);
        const u64 Ddi = f2fma(nOneP, Qdi, Pdi);
        const u64 Gdr = f2fma(c2P, Ddr, f2mul(sahP, Ydr));
        const u64 Gdi = f2fma(c2P, Ddi, f2mul(sahP, Ydi));
        const u64 nYdr = f2fma(caE1P, Ydr, f2mul(nsaE1P, Ddr));
        const u64 nYdi = f2fma(caE1P, Ydi, f2mul(nsaE1P, Ddi));
        const u64 Fpdr = f2add(Qdr, Gdr);
        const u64 Fpdi = f2add(Qdi, Gdi);
        const u64 Fmdr = f2fma(nOneP, Gdr, Pdr);
        const u64 Fmdi = f2fma(nOneP, Gdi, Pdi);
        const u64 nPdr = f2fma(sA,  Fpdi, f2mul(cA, Fpdr));
        const u64 nPdi = f2fma(nsA, Fpdr, f2mul(cA, Fpdi));
        const u64 nQdr = f2fma(nsA, Fmdi, f2mul(cA, Fmdr));
        const u64 nQdi = f2fma(sA,  Fmdr, f2mul(cA, Fmdi));

        // ---- shift ----
        float PalR, PahR, PalI, PahI, PblR, PbhR, PblI, PbhI;
        float PclR, PchR, PclI, PchI, PdlR, PdhR, PdlI, PdhI;
        upk2(nPar, PalR, PahR); upk2(nPai, PalI, PahI);
        upk2(nPbr, PblR, PbhR); upk2(nPbi, PblI, PbhI);
        upk2(nPcr, PclR, PchR); upk2(nPci, PclI, PchI);
        upk2(nPdr, PdlR, PdhR); upk2(nPdi, PdlI, PdhI);
        float QalR, QahR, QalI, QahI, QblR, QbhR, QblI, QbhI;
        float QclR, QchR, QclI, QchI, QdlR, QdhR, QdlI, QdhI;
        upk2(nQar, QalR, QahR); upk2(nQai, QalI, QahI);
        upk2(nQbr, QblR, QbhR); upk2(nQbi, QblI, QbhI);
        upk2(nQcr, QclR, QchR); upk2(nQci, QclI, QchI);
        upk2(nQdr, QdlR, QdhR); upk2(nQdi, QdlI, QdhI);

        float su_r = __shfl_up_sync(FULLMASK, PdhR, 1, 8);
        float su_i = __shfl_up_sync(FULLMASK, PdhI, 1, 8);
        float sd_r = __shfl_down_sync(FULLMASK, QalR, 1, 8);
        float sd_i = __shfl_down_sync(FULLMASK, QalI, 1, 8);
        // gl==7 shfl_down clamp returns own Fm[8gl] = Fm[56] == 0 (induction).

        // gl==0: Fp'[0] = nQ[1] * e^{-2i phi'}  (nQ[1] = own slot-a hi)
        const float spec_r = QahR * sp.x + QahI * sp.y;
        const float spec_i = QahI * sp.x - QahR * sp.y;
        if (gl == 0) { su_r = spec_r; su_i = spec_i; }

        Par = pk2(su_r, PalR);  Pai = pk2(su_i, PalI);
        Pbr = pk2(PahR, PblR);  Pbi = pk2(PahI, PblI);
        Pcr = pk2(PbhR, PclR);  Pci = pk2(PbhI, PclI);
        Pdr = pk2(PchR, PdlR);  Pdi = pk2(PchI, PdlI);
        Qar = pk2(QahR, QblR);  Qai = pk2(QahI, QblI);
        Qbr = pk2(QbhR, QclR);  Qbi = pk2(QbhI, QclI);
        Qcr = pk2(QchR, QdlR);  Qci = pk2(QchI, QdlI);
        Qdr = pk2(QdhR, sd_r);  Qdi = pk2(QdhI, sd_i);
        Yar = nYar; Yai = nYai; Ybr = nYbr; Ybi = nYbi;
        Ycr = nYcr; Yci = nYci; Ydr = nYdr; Ydi = nYdi;
    }

    // Final pulse: signal = |(Q + G)[0]|  (gl==0, slot a, lo word)
    {
        float P0r, P0i, Q0r, Q0i, Y0r, Y0i, dum;
        upk2(Par, P0r, dum); upk2(Pai, P0i, dum);
        upk2(Qar, Q0r, dum); upk2(Qai, Q0i, dum);
        upk2(Yar, Y0r, dum); upk2(Yai, Y0i, dum);
        const float D0r = P0r - Q0r;
        const float D0i = P0i - Q0i;
        const float G0r = c2 * D0r + sah * Y0r;
        const float G0i = c2 * D0i + sah * Y0i;
        const float Fp0r = Q0r + G0r;
        const float Fp0i = Q0i + G0i;
        if (gl == 0 && v < n) out[v] = sqrtf(Fp0r * Fp0r + Fp0i * Fp0i);
    }
}

extern "C" void kernel_launch(void* const* d_in, const int* in_sizes, int n_in,
                              void* d_out, int out_size)
{
    const float* T1    = (const float*)d_in[0];
    const float* T2    = (const float*)d_in[1];
    const float* alpha = (const float*)d_in[2];
    const float* TR    = (const float*)d_in[3];
    float* out = (float*)d_out;

    const int n = in_sizes[0];
    trig_init_kernel<<<1, 256>>>();

    void *p_ctab = 0, *p_gtab = 0, *p_cspec = 0, *p_gspec = 0;
    cudaGetSymbolAddress(&p_ctab,  c_tab4);
    cudaGetSymbolAddress(&p_gtab,  g_tab4);
    cudaGetSymbolAddress(&p_cspec, c_spec2);
    cudaGetSymbolAddress(&p_gspec, g_spec2);
    cudaMemcpyAsync(p_ctab,  p_gtab,  sizeof(float4) * NP, cudaMemcpyDeviceToDevice);
    cudaMemcpyAsync(p_cspec, p_gspec, sizeof(float2) * NP, cudaMemcpyDeviceToDevice);

    const int threads = 256;                   // 8 warps = 32 voxels per block
    const int vpb = (threads / 32) * 4;
    const int blocks = (n + vpb - 1) / vpb;
    epg_kernel<<<blocks, threads>>>(T1, T2, alpha, TR, out, n);
}

// round 16
// speedup vs baseline: 1.3478x; 1.1108x over previous
#include <cuda_runtime.h>

// EPG / RF-spoiled SPGR, round 16. vs R15 (1372us): Y rescale — track
// Ỹ = (sa/2)*Y = -i*sa*Z instead of Y=-2iZ, so G = c2*D + Ỹ is a single
// packed fma per component (was mul+fma): 91 -> 83 packed fma-pipe ops per
// warp-pulse. Ỹ' = caE1*Ỹ - (sa^2/2*E1)*D; boost/init scaled by sa/2.
// Everything else identical to R15: 4 voxels/warp, 8-lane groups, 8 states
// per lane (4 f32x2 slots), 1 SHFL per voxel-pulse, rotating frame,
// lazy truncation (only Fp[49] = gl6 slot-a hi killed), constant-memory
// trig tables.

#define FULLMASK 0xffffffffu
typedef unsigned long long u64;
#define NP 200

__device__    float4 g_tab4[NP];   // {cos d, cos d, sin d, sin d}
__device__    float2 g_spec2[NP];  // {cos 2phi', sin 2phi'}
__constant__  float4 c_tab4[NP];
__constant__  float2 c_spec2[NP];

__global__ void trig_init_kernel() {
    int p = threadIdx.x + blockIdx.x * blockDim.x;
    if (p >= NP) return;
    const float SPOIL = 2.0420352248333655f;  // float32(deg2rad(117))
    float phi = 0.f, inc = 0.f;
    for (int j = 0; j < p; ++j) { inc += SPOIL; phi += inc; }   // phi_p, exact ref order
    float phin = phi + (inc + SPOIL);                            // phi_{p+1}
    float d = phin - phi;                                        // exact subtraction
    float sd, cd;  sincosf(d, &sd, &cd);
    float s2p, c2p; sincosf(2.0f * phin, &s2p, &c2p);
    g_tab4[p]  = make_float4(cd, cd, sd, sd);
    g_spec2[p] = make_float2(c2p, s2p);
}

static __device__ __forceinline__ u64 pk2(float lo, float hi) {
    u64 r; asm("mov.b64 %0, {%1, %2};" : "=l"(r) : "f"(lo), "f"(hi)); return r;
}
static __device__ __forceinline__ void upk2(u64 v, float& lo, float& hi) {
    asm("mov.b64 {%0, %1}, %2;" : "=f"(lo), "=f"(hi) : "l"(v));
}
static __device__ __forceinline__ u64 f2fma(u64 a, u64 b, u64 c) {
    u64 d; asm("fma.rn.f32x2 %0, %1, %2, %3;" : "=l"(d) : "l"(a), "l"(b), "l"(c)); return d;
}
static __device__ __forceinline__ u64 f2mul(u64 a, u64 b) {
    u64 d; asm("mul.rn.f32x2 %0, %1, %2;" : "=l"(d) : "l"(a), "l"(b)); return d;
}
static __device__ __forceinline__ u64 f2add(u64 a, u64 b) {
    u64 d; asm("add.rn.f32x2 %0, %1, %2;" : "=l"(d) : "l"(a), "l"(b)); return d;
}

__global__ void __launch_bounds__(256)
epg_kernel(const float* __restrict__ T1, const float* __restrict__ T2,
           const float* __restrict__ alpha, const float* __restrict__ TR,
           float* __restrict__ out, int n)
{
    const int wid  = (blockIdx.x * blockDim.x + threadIdx.x) >> 5;
    const int lane = threadIdx.x & 31;
    const int gl   = lane & 7;                // lane within 8-lane group
    const int v    = wid * 4 + (lane >> 3);   // this lane's voxel
    const int vc   = v < n ? v : n - 1;       // clamped for loads

    const float TRv = TR[0];
    const float E1  = expf(-TRv / T1[vc]);
    const float E2  = expf(-TRv / T2[vc]);
    const float a   = alpha[vc];
    float sa, ca; sincosf(a, &sa, &ca);
    const float c2   = 0.5f * (1.0f + ca);    // cos^2(a/2)
    const float sah  = 0.5f * sa;
    const float caE1 = ca * E1;
    const float nSS  = -sah * (sa * E1);      // -(sa^2/2)*E1

    const u64 c2P    = pk2(c2, c2);
    const u64 caE1P  = pk2(caE1, caE1);
    const u64 nSSP   = pk2(nSS, nSS);
    const u64 E2P    = pk2(E2, E2);
    const u64 nE2P   = pk2(-E2, -E2);
    const u64 nOneP  = pk2(-1.f, -1.f);
    const u64 boostP = pk2(gl == 0 ? -2.0f * sah * (1.0f - E1) : 0.f, 0.f);

    // Lazy truncation: Fp[49] = gl 6, slot a, hi word.
    const u64 mK = (gl == 6) ? 0x00000000ffffffffull : ~0ull;

    // State: slots a..d = {k=8gl+0,1}, {+2,3}, {+4,5}, {+6,7}.
    // Ỹ = -i*sa*Z (scaled Y); init Z[0]=1 -> Ỹi[0] = -2*sah = -sa.
    u64 Par = 0, Pai = 0, Pbr = 0, Pbi = 0, Pcr = 0, Pci = 0, Pdr = 0, Pdi = 0;
    u64 Qar = 0, Qai = 0, Qbr = 0, Qbi = 0, Qcr = 0, Qci = 0, Qdr = 0, Qdi = 0;
    u64 Yar = 0, Yai = pk2(gl == 0 ? -2.0f * sah : 0.f, 0.f);
    u64 Ybr = 0, Ybi = 0, Ycr = 0, Yci = 0, Ydr = 0, Ydi = 0;

    #pragma unroll 2
    for (int p = 0; p < NP - 1; ++p) {
        const float4 t = c_tab4[p];                 // {cd,cd,sd,sd} (uniform LDC)
        const u64 cdP = pk2(t.x, t.y);
        const u64 sdP = pk2(t.z, t.w);
        const float2 sp = c_spec2[p];               // {cos 2phi', sin 2phi'}

        // Coefficients (shared by all 4 slots): A = E2 * e^{-i d}
        const u64 cA  = f2mul(E2P, cdP);
        const u64 sA  = f2mul(E2P, sdP);
        const u64 nsA = f2mul(nE2P, sdP);

        // ---- slot a (carries boost in Ỹi) ----
        const u64 Dar = f2fma(nOneP, Qar, Par);
        const u64 Dai = f2fma(nOneP, Qai, Pai);
        const u64 Gar = f2fma(c2P, Dar, Yar);
        const u64 Gai = f2fma(c2P, Dai, Yai);
        const u64 nYar = f2fma(caE1P, Yar, f2mul(nSSP, Dar));
        const u64 nYai = f2fma(caE1P, Yai, f2fma(nSSP, Dai, boostP));
        const u64 Fpar = f2add(Qar, Gar);
        const u64 Fpai = f2add(Qai, Gai);
        const u64 Fmar = f2fma(nOneP, Gar, Par);
        const u64 Fmai = f2fma(nOneP, Gai, Pai);
        const u64 nPar = f2fma(sA,  Fpai, f2mul(cA, Fpar)) & mK;
        const u64 nPai = f2fma(nsA, Fpar, f2mul(cA, Fpai)) & mK;
        const u64 nQar = f2fma(nsA, Fmai, f2mul(cA, Fmar));
        const u64 nQai = f2fma(sA,  Fmar, f2mul(cA, Fmai));

        // ---- slot b ----
        const u64 Dbr = f2fma(nOneP, Qbr, Pbr);
        const u64 Dbi = f2fma(nOneP, Qbi, Pbi);
        const u64 Gbr = f2fma(c2P, Dbr, Ybr);
        const u64 Gbi = f2fma(c2P, Dbi, Ybi);
        const u64 nYbr = f2fma(caE1P, Ybr, f2mul(nSSP, Dbr));
        const u64 nYbi = f2fma(caE1P, Ybi, f2mul(nSSP, Dbi));
        const u64 Fpbr = f2add(Qbr, Gbr);
        const u64 Fpbi = f2add(Qbi, Gbi);
        const u64 Fmbr = f2fma(nOneP, Gbr, Pbr);
        const u64 Fmbi = f2fma(nOneP, Gbi, Pbi);
        const u64 nPbr = f2fma(sA,  Fpbi, f2mul(cA, Fpbr));
        const u64 nPbi = f2fma(nsA, Fpbr, f2mul(cA, Fpbi));
        const u64 nQbr = f2fma(nsA, Fmbi, f2mul(cA, Fmbr));
        const u64 nQbi = f2fma(sA,  Fmbr, f2mul(cA, Fmbi));

        // ---- slot c ----
        const u64 Dcr = f2fma(nOneP, Qcr, Pcr);
        const u64 Dci = f2fma(nOneP, Qci, Pci);
        const u64 Gcr = f2fma(c2P, Dcr, Ycr);
        const u64 Gci = f2fma(c2P, Dci, Yci);
        const u64 nYcr = f2fma(caE1P, Ycr, f2mul(nSSP, Dcr));
        const u64 nYci = f2fma(caE1P, Yci, f2mul(nSSP, Dci));
        const u64 Fpcr = f2add(Qcr, Gcr);
        const u64 Fpci = f2add(Qci, Gci);
        const u64 Fmcr = f2fma(nOneP, Gcr, Pcr);
        const u64 Fmci = f2fma(nOneP, Gci, Pci);
        const u64 nPcr = f2fma(sA,  Fpci, f2mul(cA, Fpcr));
        const u64 nPci = f2fma(nsA, Fpcr, f2mul(cA, Fpci));
        const u64 nQcr = f2fma(nsA, Fmci, f2mul(cA, Fmcr));
        const u64 nQci = f2fma(sA,  Fmcr, f2mul(cA, Fmci));

        // ---- slot d ----
        const u64 Ddr = f2fma(nOneP, Qdr, Pdr);
        const u64 Ddi = f2fma(nOneP, Qdi, Pdi);
        const u64 Gdr = f2fma(c2P, Ddr, Ydr);
        const u64 Gdi = f2fma(c2P, Ddi, Ydi);
        const u64 nYdr = f2fma(caE1P, Ydr, f2mul(nSSP, Ddr));
        const u64 nYdi = f2fma(caE1P, Ydi, f2mul(nSSP, Ddi));
        const u64 Fpdr = f2add(Qdr, Gdr);
        const u64 Fpdi = f2add(Qdi, Gdi);
        const u64 Fmdr = f2fma(nOneP, Gdr, Pdr);
        const u64 Fmdi = f2fma(nOneP, Gdi, Pdi);
        const u64 nPdr = f2fma(sA,  Fpdi, f2mul(cA, Fpdr));
        const u64 nPdi = f2fma(nsA, Fpdr, f2mul(cA, Fpdi));
        const u64 nQdr = f2fma(nsA, Fmdi, f2mul(cA, Fmdr));
        const u64 nQdi = f2fma(sA,  Fmdr, f2mul(cA, Fmdi));

        // ---- shift ----
        float PalR, PahR, PalI, PahI, PblR, PbhR, PblI, PbhI;
        float PclR, PchR, PclI, PchI, PdlR, PdhR, PdlI, PdhI;
        upk2(nPar, PalR, PahR); upk2(nPai, PalI, PahI);
        upk2(nPbr, PblR, PbhR); upk2(nPbi, PblI, PbhI);
        upk2(nPcr, PclR, PchR); upk2(nPci, PclI, PchI);
        upk2(nPdr, PdlR, PdhR); upk2(nPdi, PdlI, PdhI);
        float QalR, QahR, QalI, QahI, QblR, QbhR, QblI, QbhI;
        float QclR, QchR, QclI, QchI, QdlR, QdhR, QdlI, QdhI;
        upk2(nQar, QalR, QahR); upk2(nQai, QalI, QahI);
        upk2(nQbr, QblR, QbhR); upk2(nQbi, QblI, QbhI);
        upk2(nQcr, QclR, QchR); upk2(nQci, QclI, QchI);
        upk2(nQdr, QdlR, QdhR); upk2(nQdi, QdlI, QdhI);

        float su_r = __shfl_up_sync(FULLMASK, PdhR, 1, 8);
        float su_i = __shfl_up_sync(FULLMASK, PdhI, 1, 8);
        float sd_r = __shfl_down_sync(FULLMASK, QalR, 1, 8);
        float sd_i = __shfl_down_sync(FULLMASK, QalI, 1, 8);
        // gl==7 shfl_down clamp returns own Fm[56] == 0 (induction). OK.

        // gl==0: Fp'[0] = nQ[1] * e^{-2i phi'}  (nQ[1] = own slot-a hi)
        const float spec_r = QahR * sp.x + QahI * sp.y;
        const float spec_i = QahI * sp.x - QahR * sp.y;
        if (gl == 0) { su_r = spec_r; su_i = spec_i; }

        Par = pk2(su_r, PalR);  Pai = pk2(su_i, PalI);
        Pbr = pk2(PahR, PblR);  Pbi = pk2(PahI, PblI);
        Pcr = pk2(PbhR, PclR);  Pci = pk2(PbhI, PclI);
        Pdr = pk2(PchR, PdlR);  Pdi = pk2(PchI, PdlI);
        Qar = pk2(QahR, QblR);  Qai = pk2(QahI, QblI);
        Qbr = pk2(QbhR, QclR);  Qbi = pk2(QbhI, QclI);
        Qcr = pk2(QchR, QdlR);  Qci = pk2(QchI, QdlI);
        Qdr = pk2(QdhR, sd_r);  Qdi = pk2(QdhI, sd_i);
        Yar = nYar; Yai = nYai; Ybr = nYbr; Ybi = nYbi;
        Ycr = nYcr; Yci = nYci; Ydr = nYdr; Ydi = nYdi;
    }

    // Final pulse: signal = |(Q + G)[0]|, G = c2*D + Ỹ (gl==0, slot a, lo)
    {
        float P0r, P0i, Q0r, Q0i, Y0r, Y0i, dum;
        upk2(Par, P0r, dum); upk2(Pai, P0i, dum);
        upk2(Qar, Q0r, dum); upk2(Qai, Q0i, dum);
        upk2(Yar, Y0r, dum); upk2(Yai, Y0i, dum);
        const float D0r = P0r - Q0r;
        const float D0i = P0i - Q0i;
        const float G0r = c2 * D0r + Y0r;
        const float G0i = c2 * D0i + Y0i;
        const float Fp0r = Q0r + G0r;
        const float Fp0i = Q0i + G0i;
        if (gl == 0 && v < n) out[v] = sqrtf(Fp0r * Fp0r + Fp0i * Fp0i);
    }
}

extern "C" void kernel_launch(void* const* d_in, const int* in_sizes, int n_in,
                              void* d_out, int out_size)
{
    const float* T1    = (const float*)d_in[0];
    const float* T2    = (const float*)d_in[1];
    const float* alpha = (const float*)d_in[2];
    const float* TR    = (const float*)d_in[3];
    float* out = (float*)d_out;

    const int n = in_sizes[0];
    trig_init_kernel<<<1, 256>>>();

    void *p_ctab = 0, *p_gtab = 0, *p_cspec = 0, *p_gspec = 0;
    cudaGetSymbolAddress(&p_ctab,  c_tab4);
    cudaGetSymbolAddress(&p_gtab,  g_tab4);
    cudaGetSymbolAddress(&p_cspec, c_spec2);
    cudaGetSymbolAddress(&p_gspec, g_spec2);
    cudaMemcpyAsync(p_ctab,  p_gtab,  sizeof(float4) * NP, cudaMemcpyDeviceToDevice);
    cudaMemcpyAsync(p_cspec, p_gspec, sizeof(float2) * NP, cudaMemcpyDeviceToDevice);

    const int threads = 256;                   // 8 warps = 32 voxels per block
    const int vpb = (threads / 32) * 4;
    const int blocks = (n + vpb - 1) / vpb;
    epg_kernel<<<blocks, threads>>>(T1, T2, alpha, TR, out, n);
}